// round 1
// baseline (speedup 1.0000x reference)
#include <cuda_runtime.h>
#include <math.h>

// One tiny kernel, one working thread. Problem size: 4x4 matrices, 12-elem state.
// Entirely launch-latency bound; the goal is a single minimal launch.

__global__ void kuramoto_kernel(const float* __restrict__ x,
                                const float* __restrict__ K,
                                const float* __restrict__ b,
                                const float* __restrict__ G,
                                const float* __restrict__ adj,
                                float* __restrict__ out)
{
    if (threadIdx.x != 0) return;

    // Load state: x1 = angles a, x2 = velocities v, xi
    float a[4], v[4], xi[4];
    #pragma unroll
    for (int i = 0; i < 4; i++) {
        a[i]  = x[i];
        v[i]  = x[4 + i];
        xi[i] = x[8 + i];
    }

    // dH = K^T @ tanh(K @ xi + b)
    float t1[4];
    #pragma unroll
    for (int i = 0; i < 4; i++) {
        float s = b[i];
        #pragma unroll
        for (int j = 0; j < 4; j++) s += K[i * 4 + j] * xi[j];
        t1[i] = tanhf(s);
    }
    float dH[4];
    #pragma unroll
    for (int i = 0; i < 4; i++) {
        float s = 0.f;
        #pragma unroll
        for (int j = 0; j < 4; j++) s += K[j * 4 + i] * t1[j];
        dH[i] = s;
    }

    // interactions[j] = sum_i adj[i][j] * cos(a[j]-a[i]) * (v[j]-v[i])
    float inter[4];
    #pragma unroll
    for (int j = 0; j < 4; j++) {
        float s = 0.f;
        #pragma unroll
        for (int i = 0; i < 4; i++) {
            s += adj[i * 4 + j] * cosf(a[j] - a[i]) * (v[j] - v[i]);
        }
        inter[j] = s;
    }

    // u = -(adj*G)^T @ dH ;  dxdt = 1.25 * u * interactions
    float dxdt[4];
    #pragma unroll
    for (int i = 0; i < 4; i++) {
        float s = 0.f;
        #pragma unroll
        for (int j = 0; j < 4; j++) s += adj[j * 4 + i] * G[j * 4 + i] * dH[j];
        dxdt[i] = 1.25f * (-s) * inter[i];
    }

    // gamma = 0.1 * lambda_max(G @ G^T) via power iteration on M = G G^T (4x4 SPD)
    float M[4][4];
    #pragma unroll
    for (int i = 0; i < 4; i++) {
        #pragma unroll
        for (int j = 0; j < 4; j++) {
            float s = 0.f;
            #pragma unroll
            for (int k = 0; k < 4; k++) s += G[i * 4 + k] * G[j * 4 + k];
            M[i][j] = s;
        }
    }
    float y[4] = {1.f, 1.f, 1.f, 1.f};
    #pragma unroll 1
    for (int it = 0; it < 64; it++) {
        float z[4];
        #pragma unroll
        for (int i = 0; i < 4; i++) {
            float s = 0.f;
            #pragma unroll
            for (int j = 0; j < 4; j++) s += M[i][j] * y[j];
            z[i] = s;
        }
        float m = fmaxf(fmaxf(fabsf(z[0]), fabsf(z[1])),
                        fmaxf(fabsf(z[2]), fabsf(z[3])));
        float inv = 1.f / m;
        #pragma unroll
        for (int i = 0; i < 4; i++) y[i] = z[i] * inv;
    }
    // Rayleigh quotient for the eigenvalue
    float num = 0.f, den = 0.f;
    #pragma unroll
    for (int i = 0; i < 4; i++) {
        float s = 0.f;
        #pragma unroll
        for (int j = 0; j < 4; j++) s += M[i][j] * y[j];
        num += y[i] * s;
        den += y[i] * y[i];
    }
    float gamma = 0.1f * (num / den);

    // dxi_dt = (J - gamma I) @ dH + (adj*G) @ x2
    // J = [[0,-1,0,0],[1,0,0,0],[0,0,0,-1],[0,0,1,0]]
    float JdH[4];
    JdH[0] = -dH[1] - gamma * dH[0];
    JdH[1] =  dH[0] - gamma * dH[1];
    JdH[2] = -dH[3] - gamma * dH[2];
    JdH[3] =  dH[2] - gamma * dH[3];

    float dxi[4];
    #pragma unroll
    for (int i = 0; i < 4; i++) {
        float s = 0.f;
        #pragma unroll
        for (int j = 0; j < 4; j++) s += adj[i * 4 + j] * G[i * 4 + j] * v[j];
        dxi[i] = JdH[i] + s;
    }

    // out = concat(x2, dxdt, dxi_dt)
    #pragma unroll
    for (int i = 0; i < 4; i++) {
        out[i]     = v[i];
        out[4 + i] = dxdt[i];
        out[8 + i] = dxi[i];
    }
}

extern "C" void kernel_launch(void* const* d_in, const int* in_sizes, int n_in,
                              void* d_out, int out_size)
{
    // metadata order: t(1), x(12), K(16), b(4), G(16), adj(16)
    const float* x   = (const float*)d_in[1];
    const float* K   = (const float*)d_in[2];
    const float* b   = (const float*)d_in[3];
    const float* G   = (const float*)d_in[4];
    const float* adj = (const float*)d_in[5];
    float* out = (float*)d_out;

    kuramoto_kernel<<<1, 32>>>(x, K, b, G, adj, out);
}

// round 2
// speedup vs baseline: 1.5581x; 1.5581x over previous
#include <cuda_runtime.h>
#include <math.h>

// Single working thread; tiny 4x4 problem, entirely serial-latency bound.
// Optimizations vs R1: matrix-squaring power method (4 squarings ≡ 16 power
// steps, Rayleigh squares the error), __cosf with symmetry (6 calls not 16),
// exp-based fast tanh, float4 loads.

__device__ __forceinline__ float fast_tanh(float s) {
    // robust: e->inf gives 1, e->0 gives -1
    float e = __expf(2.0f * s);
    return 1.0f - __fdividef(2.0f, e + 1.0f);
}

__global__ void __launch_bounds__(32, 1)
kuramoto_kernel(const float* __restrict__ x,
                const float* __restrict__ Kp,
                const float* __restrict__ bp,
                const float* __restrict__ Gp,
                const float* __restrict__ adjp,
                float* __restrict__ out)
{
    if (threadIdx.x != 0) return;

    // ---- vectorized loads (front-batched for MLP) ----
    const float4* x4 = (const float4*)x;
    float4 xa = x4[0], xv = x4[1], xx = x4[2];
    float4 Kr0 = ((const float4*)Kp)[0], Kr1 = ((const float4*)Kp)[1],
           Kr2 = ((const float4*)Kp)[2], Kr3 = ((const float4*)Kp)[3];
    float4 Gr0 = ((const float4*)Gp)[0], Gr1 = ((const float4*)Gp)[1],
           Gr2 = ((const float4*)Gp)[2], Gr3 = ((const float4*)Gp)[3];
    float4 Ar0 = ((const float4*)adjp)[0], Ar1 = ((const float4*)adjp)[1],
           Ar2 = ((const float4*)adjp)[2], Ar3 = ((const float4*)adjp)[3];
    float4 bb = ((const float4*)bp)[0];

    float a[4]  = {xa.x, xa.y, xa.z, xa.w};
    float v[4]  = {xv.x, xv.y, xv.z, xv.w};
    float xi[4] = {xx.x, xx.y, xx.z, xx.w};
    float K[16] = {Kr0.x,Kr0.y,Kr0.z,Kr0.w, Kr1.x,Kr1.y,Kr1.z,Kr1.w,
                   Kr2.x,Kr2.y,Kr2.z,Kr2.w, Kr3.x,Kr3.y,Kr3.z,Kr3.w};
    float G[16] = {Gr0.x,Gr0.y,Gr0.z,Gr0.w, Gr1.x,Gr1.y,Gr1.z,Gr1.w,
                   Gr2.x,Gr2.y,Gr2.z,Gr2.w, Gr3.x,Gr3.y,Gr3.z,Gr3.w};
    float A[16] = {Ar0.x,Ar0.y,Ar0.z,Ar0.w, Ar1.x,Ar1.y,Ar1.z,Ar1.w,
                   Ar2.x,Ar2.y,Ar2.z,Ar2.w, Ar3.x,Ar3.y,Ar3.z,Ar3.w};
    float bv[4] = {bb.x, bb.y, bb.z, bb.w};

    // ---- dH = K^T tanh(K xi + b) ----
    float t1[4];
    #pragma unroll
    for (int i = 0; i < 4; i++) {
        float s = bv[i];
        #pragma unroll
        for (int j = 0; j < 4; j++) s = fmaf(K[i*4+j], xi[j], s);
        t1[i] = fast_tanh(s);
    }
    float dH[4];
    #pragma unroll
    for (int i = 0; i < 4; i++) {
        float s = 0.f;
        #pragma unroll
        for (int j = 0; j < 4; j++) s = fmaf(K[j*4+i], t1[j], s);
        dH[i] = s;
    }

    // ---- interactions: cos symmetric, 6 unique values ----
    float c[4][4];
    c[0][0] = c[1][1] = c[2][2] = c[3][3] = 1.0f;
    c[0][1] = c[1][0] = __cosf(a[0] - a[1]);
    c[0][2] = c[2][0] = __cosf(a[0] - a[2]);
    c[0][3] = c[3][0] = __cosf(a[0] - a[3]);
    c[1][2] = c[2][1] = __cosf(a[1] - a[2]);
    c[1][3] = c[3][1] = __cosf(a[1] - a[3]);
    c[2][3] = c[3][2] = __cosf(a[2] - a[3]);

    // interactions[j] = sum_i adj[i][j] * cos(a[j]-a[i]) * (v[j]-v[i])
    float inter[4];
    #pragma unroll
    for (int j = 0; j < 4; j++) {
        float s = 0.f;
        #pragma unroll
        for (int i = 0; i < 4; i++)
            s = fmaf(A[i*4+j] * c[i][j], v[j] - v[i], s);
        inter[j] = s;
    }

    // ---- dxdt = 1.25 * (-(adj*G)^T dH) * inter ----
    float dxdt[4];
    #pragma unroll
    for (int i = 0; i < 4; i++) {
        float s = 0.f;
        #pragma unroll
        for (int j = 0; j < 4; j++) s = fmaf(A[j*4+i] * G[j*4+i], dH[j], s);
        dxdt[i] = -1.25f * s * inter[i];
    }

    // ---- gamma = 0.1 * lambda_max(G G^T) via matrix squaring ----
    float M[16];
    #pragma unroll
    for (int i = 0; i < 4; i++) {
        #pragma unroll
        for (int j = 0; j < 4; j++) {
            float s = 0.f;
            #pragma unroll
            for (int k = 0; k < 4; k++) s = fmaf(G[i*4+k], G[j*4+k], s);
            M[i*4+j] = s;
        }
    }
    // P = M^16 via 4 squarings (16 independent dot products each -> high ILP)
    float P[16], Q[16];
    #pragma unroll
    for (int i = 0; i < 16; i++) P[i] = M[i];
    #pragma unroll
    for (int sq = 0; sq < 4; sq++) {
        #pragma unroll
        for (int i = 0; i < 4; i++) {
            #pragma unroll
            for (int j = 0; j < 4; j++) {
                float s = 0.f;
                #pragma unroll
                for (int k = 0; k < 4; k++) s = fmaf(P[i*4+k], P[k*4+j], s);
                Q[i*4+j] = s;
            }
        }
        #pragma unroll
        for (int i = 0; i < 16; i++) P[i] = Q[i];
    }
    // w = M^16 @ ones  (16 power steps; Perron vector has big overlap with ones)
    float w[4];
    #pragma unroll
    for (int i = 0; i < 4; i++)
        w[i] = P[i*4+0] + P[i*4+1] + P[i*4+2] + P[i*4+3];
    // normalize to avoid overflow in dot products
    float m = fmaxf(fmaxf(fabsf(w[0]), fabsf(w[1])),
                    fmaxf(fabsf(w[2]), fabsf(w[3])));
    float invm = __frcp_rn(m);
    #pragma unroll
    for (int i = 0; i < 4; i++) w[i] *= invm;
    // Rayleigh quotient: lambda ~= (w^T M w) / (w^T w)
    float num = 0.f, den = 0.f;
    #pragma unroll
    for (int i = 0; i < 4; i++) {
        float s = 0.f;
        #pragma unroll
        for (int j = 0; j < 4; j++) s = fmaf(M[i*4+j], w[j], s);
        num = fmaf(w[i], s, num);
        den = fmaf(w[i], w[i], den);
    }
    float gamma = 0.1f * __fdividef(num, den);

    // ---- dxi_dt = (J - gamma I) dH + (adj*G) x2 ----
    float JdH[4];
    JdH[0] = fmaf(-gamma, dH[0], -dH[1]);
    JdH[1] = fmaf(-gamma, dH[1],  dH[0]);
    JdH[2] = fmaf(-gamma, dH[2], -dH[3]);
    JdH[3] = fmaf(-gamma, dH[3],  dH[2]);

    float dxi[4];
    #pragma unroll
    for (int i = 0; i < 4; i++) {
        float s = 0.f;
        #pragma unroll
        for (int j = 0; j < 4; j++) s = fmaf(A[i*4+j] * G[i*4+j], v[j], s);
        dxi[i] = JdH[i] + s;
    }

    // ---- out = concat(x2, dxdt, dxi_dt) as float4 stores ----
    float4* o4 = (float4*)out;
    o4[0] = make_float4(v[0], v[1], v[2], v[3]);
    o4[1] = make_float4(dxdt[0], dxdt[1], dxdt[2], dxdt[3]);
    o4[2] = make_float4(dxi[0], dxi[1], dxi[2], dxi[3]);
}

extern "C" void kernel_launch(void* const* d_in, const int* in_sizes, int n_in,
                              void* d_out, int out_size)
{
    // metadata order: t(1), x(12), K(16), b(4), G(16), adj(16)
    const float* x   = (const float*)d_in[1];
    const float* K   = (const float*)d_in[2];
    const float* b   = (const float*)d_in[3];
    const float* G   = (const float*)d_in[4];
    const float* adj = (const float*)d_in[5];
    float* out = (float*)d_out;

    kuramoto_kernel<<<1, 32>>>(x, K, b, G, adj, out);
}